// round 7
// baseline (speedup 1.0000x reference)
#include <cuda_runtime.h>
#include <cuda_bf16.h>
#include <stdint.h>
#include <math.h>

#define M_TOK 16384
#define N_EMB 16384
#define KDIM  256
#define HWSZ  1024
#define NZ    (M_TOK * KDIM)
#define FIXLEN 30.0f

#define NUM_CTAS   152
#define RUNS_TOTAL 2048   /* 128 m-tiles x 16 runs; run = 8 n-subtiles of 128 */

// ---------------- device scratch (static, no allocation) ----------------
__device__ float          g_zflat[M_TOK * KDIM];
__device__ __nv_bfloat16  g_z_hi[M_TOK * KDIM];
__device__ __nv_bfloat16  g_z_lo[M_TOK * KDIM];
__device__ __nv_bfloat16  g_e_hi[N_EMB * KDIM];
__device__ __nv_bfloat16  g_e_lo[N_EMB * KDIM];
__device__ float          g_enorm2[N_EMB];
__device__ unsigned long long g_best[M_TOK];   // packed (ordered-float << 32) | idx
__device__ unsigned       g_unit_ctr;
__device__ float          g_normpart[64];
__device__ float          g_scalars[2];
__device__ float          g_diffpart[256];

// ---------------- small helpers ----------------
__device__ __forceinline__ uint32_t smem_u32(const void* p) {
    uint32_t a;
    asm("{ .reg .u64 t; cvta.to.shared.u64 t, %1; cvt.u32.u64 %0, t; }" : "=r"(a) : "l"(p));
    return a;
}
__device__ __forceinline__ void cp_async16(uint32_t dst, const void* src) {
    uint64_t g = __cvta_generic_to_global(src);
    asm volatile("cp.async.cg.shared.global [%0], [%1], 16;" :: "r"(dst), "l"(g));
}
__device__ __forceinline__ void cp_commit() { asm volatile("cp.async.commit_group;"); }
template <int N> __device__ __forceinline__ void cp_wait() {
    asm volatile("cp.async.wait_group %0;" :: "n"(N));
}
__device__ __forceinline__ void ldsm4(uint32_t* r, uint32_t addr) {
    asm volatile("ldmatrix.sync.aligned.m8n8.x4.shared.b16 {%0,%1,%2,%3}, [%4];"
                 : "=r"(r[0]), "=r"(r[1]), "=r"(r[2]), "=r"(r[3]) : "r"(addr));
}
__device__ __forceinline__ void mma16816(float* c, const uint32_t* a, uint32_t b0, uint32_t b1) {
    asm volatile("mma.sync.aligned.m16n8k16.row.col.f32.bf16.bf16.f32 "
                 "{%0,%1,%2,%3}, {%4,%5,%6,%7}, {%8,%9}, {%0,%1,%2,%3};"
                 : "+f"(c[0]), "+f"(c[1]), "+f"(c[2]), "+f"(c[3])
                 : "r"(a[0]), "r"(a[1]), "r"(a[2]), "r"(a[3]), "r"(b0), "r"(b1));
}
__device__ __forceinline__ unsigned long long pack_key(float v, unsigned idx) {
    unsigned u = __float_as_uint(v);
    u = (u & 0x80000000u) ? ~u : (u | 0x80000000u);
    return ((unsigned long long)u << 32) | idx;
}

__device__ __forceinline__ void split4(float4 v, uint2& ph, uint2& pl) {
    __nv_bfloat16 h0 = __float2bfloat16(v.x), h1 = __float2bfloat16(v.y),
                  h2 = __float2bfloat16(v.z), h3 = __float2bfloat16(v.w);
    __nv_bfloat16 l0 = __float2bfloat16(v.x - __bfloat162float(h0));
    __nv_bfloat16 l1 = __float2bfloat16(v.y - __bfloat162float(h1));
    __nv_bfloat16 l2 = __float2bfloat16(v.z - __bfloat162float(h2));
    __nv_bfloat16 l3 = __float2bfloat16(v.w - __bfloat162float(h3));
    ph.x = (uint32_t)__bfloat16_as_ushort(h0) | ((uint32_t)__bfloat16_as_ushort(h1) << 16);
    ph.y = (uint32_t)__bfloat16_as_ushort(h2) | ((uint32_t)__bfloat16_as_ushort(h3) << 16);
    pl.x = (uint32_t)__bfloat16_as_ushort(l0) | ((uint32_t)__bfloat16_as_ushort(l1) << 16);
    pl.y = (uint32_t)__bfloat16_as_ushort(l2) | ((uint32_t)__bfloat16_as_ushort(l3) << 16);
}

// ---------------- kernel 1: transpose z, token norms, bf16 split ----------------
__global__ void k_prep(const float* __restrict__ z) {
    int t  = blockIdx.x * 256 + threadIdx.x;
    int b  = t >> 10;
    int hw = t & 1023;
    const float* zp = z + (size_t)b * (KDIM * HWSZ) + hw;
    float acc = 0.0f;
    g_best[t] = 0xFFFFFFFFFFFFFFFFull;
#pragma unroll 4
    for (int c = 0; c < KDIM; c += 4) {
        float v0 = zp[(c + 0) * HWSZ];
        float v1 = zp[(c + 1) * HWSZ];
        float v2 = zp[(c + 2) * HWSZ];
        float v3 = zp[(c + 3) * HWSZ];
        acc += v0 * v0 + v1 * v1 + v2 * v2 + v3 * v3;
        float4 w = make_float4(v0, v1, v2, v3);
        *(float4*)&g_zflat[t * KDIM + c] = w;
        uint2 ph, pl; split4(w, ph, pl);
        *(uint2*)&g_z_hi[t * KDIM + c] = ph;
        *(uint2*)&g_z_lo[t * KDIM + c] = pl;
    }
    float nrm = sqrtf(acc);
    __shared__ float sred[256];
    sred[threadIdx.x] = nrm;
    __syncthreads();
    for (int s = 128; s > 0; s >>= 1) {
        if (threadIdx.x < s) sred[threadIdx.x] += sred[threadIdx.x + s];
        __syncthreads();
    }
    if (threadIdx.x == 0) g_normpart[blockIdx.x] = sred[0];
}

// ---------------- kernel 2: scale + counter reset ----------------
__global__ void k_scale() {
    __shared__ float s[64];
    s[threadIdx.x] = g_normpart[threadIdx.x];
    __syncthreads();
    for (int st = 32; st > 0; st >>= 1) {
        if (threadIdx.x < st) s[threadIdx.x] += s[threadIdx.x + st];
        __syncthreads();
    }
    if (threadIdx.x == 0) {
        float pre_len = s[0] / (float)M_TOK;
        float scale = (pre_len >= FIXLEN) ? (FIXLEN / pre_len) : 1.0f;
        g_scalars[0] = scale;
        g_scalars[1] = 2.0f * scale / FIXLEN;
        g_unit_ctr = 0u;
    }
}

// ---------------- kernel 3 ----------------
__global__ void k_enorm(const float* __restrict__ emb) {
    int w    = threadIdx.x >> 5;
    int lane = threadIdx.x & 31;
    int r    = blockIdx.x * 8 + w;
    const float4* ep = (const float4*)(emb + (size_t)r * KDIM);
    float4 a = ep[lane];
    float4 b = ep[lane + 32];
    float acc = a.x * a.x + a.y * a.y + a.z * a.z + a.w * a.w
              + b.x * b.x + b.y * b.y + b.z * b.z + b.w * b.w;
    uint2 ph, pl;
    split4(a, ph, pl);
    *(uint2*)&g_e_hi[(size_t)r * KDIM + 4 * lane] = ph;
    *(uint2*)&g_e_lo[(size_t)r * KDIM + 4 * lane] = pl;
    split4(b, ph, pl);
    *(uint2*)&g_e_hi[(size_t)r * KDIM + 128 + 4 * lane] = ph;
    *(uint2*)&g_e_lo[(size_t)r * KDIM + 128 + 4 * lane] = pl;
#pragma unroll
    for (int s = 16; s > 0; s >>= 1)
        acc += __shfl_down_sync(0xffffffffu, acc, s);
    if (lane == 0) g_enorm2[r] = acc;
}

// ---------------- kernel 4: persistent HMMA bf16x3 GEMM + fused argmin ----------------
#define SM_A_BYTES 131072
#define SM_B_BYTES 32768

__device__ __forceinline__ uint32_t a_sw(int row, int col) {   // col in [0,512)
    return (uint32_t)(row * 1024 + ((col >> 6) << 7)
           + (((((col >> 3) & 7) ^ (row & 7))) << 4) + ((col & 7) << 1));
}
__device__ __forceinline__ uint32_t b_sw(int row, int col) {   // col in [0,128)
    return (uint32_t)(row * 256 + ((col >> 6) << 7)
           + (((((col >> 3) & 7) ^ (row & 7))) << 4) + ((col & 7) << 1));
}

extern __shared__ char dsm[];

// DUAL: e_hi chunk vs a_hi AND a_lo; !DUAL: e_lo chunk vs a_hi.
// Addresses: precomputed per-thread offsets; kk phases = kk&3, +128 for kk>=4,
// +abase2 (=2*abase) for the second 128-k block, +512 for the lo copy of A.
template <bool DUAL>
__device__ __forceinline__ void pass_t(
    uint32_t As, uint32_t Bb, uint32_t abase2,
    const uint32_t* aoff0, const uint32_t* aoff1,
    const uint32_t* boff0, const uint32_t* boff1,
    float acc[2][4][4])
{
    const uint32_t* aoff[2] = { aoff0, aoff1 };
    const uint32_t* boff[2] = { boff0, boff1 };
    uint32_t ah[2][2][4], al[2][2][4], br[2][2][4];
#pragma unroll
    for (int mt = 0; mt < 2; mt++) {
        ldsm4(ah[0][mt], As + aoff[mt][0] + abase2);
        if (DUAL) ldsm4(al[0][mt], As + aoff[mt][0] + abase2 + 512u);
    }
#pragma unroll
    for (int np = 0; np < 2; np++)
        ldsm4(br[0][np], Bb + boff[np][0]);
#pragma unroll
    for (int kk = 0; kk < 8; kk++) {
        const int cur = kk & 1, nxt = cur ^ 1;
        if (kk < 7) {
            const uint32_t hi = ((kk + 1) & 4) ? 128u : 0u;
            const int ph = (kk + 1) & 3;
#pragma unroll
            for (int mt = 0; mt < 2; mt++) {
                ldsm4(ah[nxt][mt], As + aoff[mt][ph] + hi + abase2);
                if (DUAL) ldsm4(al[nxt][mt], As + aoff[mt][ph] + hi + abase2 + 512u);
            }
#pragma unroll
            for (int np = 0; np < 2; np++)
                ldsm4(br[nxt][np], Bb + boff[np][ph] + hi);
        }
#pragma unroll
        for (int mt = 0; mt < 2; mt++)
#pragma unroll
            for (int nt = 0; nt < 4; nt++)
                mma16816(acc[mt][nt], ah[cur][mt],
                         br[cur][nt >> 1][(nt & 1) * 2], br[cur][nt >> 1][(nt & 1) * 2 + 1]);
        if (DUAL) {
#pragma unroll
            for (int mt = 0; mt < 2; mt++)
#pragma unroll
                for (int nt = 0; nt < 4; nt++)
                    mma16816(acc[mt][nt], al[cur][mt],
                             br[cur][nt >> 1][(nt & 1) * 2], br[cur][nt >> 1][(nt & 1) * 2 + 1]);
        }
    }
}

__global__ void __launch_bounds__(512, 1) k_gemm_p() {
    __shared__ unsigned s_run;

    const int tid  = threadIdx.x;
    const int lane = tid & 31;
    const int wid  = tid >> 5;
    const int wm   = wid & 3;
    const int wn   = wid >> 2;
    const int g    = lane >> 2;
    const int cc   = lane & 3;
    const int sub  = lane >> 3;
    const int r8   = lane & 7;

    uint32_t raw  = smem_u32(dsm);
    uint32_t base = (raw + 255u) & ~255u;
    const uint32_t As = base;
    const uint32_t Bbuf0 = base + SM_A_BYTES;

    const int arow_base = wm * 32 + ((sub & 1) << 3) + r8;
    const int ak8       = (sub >> 1) & 1;           // akof>>3
    const int brow_base = wn * 32 + ((sub >> 1) << 3) + r8;
    const int bk8       = sub & 1;                  // bkof>>3

    // Precomputed LDSM offsets (phase = kk&3; +128 when kk>=4; A: +abase2, +512 lo)
    uint32_t aoff0[4], aoff1[4], boff0[4], boff1[4];
#pragma unroll
    for (int ph = 0; ph < 4; ph++) {
        int ar0 = arow_base, ar1 = arow_base + 16;
        aoff0[ph] = (uint32_t)(ar0 * 1024 + ((((2 * ph + ak8) & 7) ^ (ar0 & 7)) << 4));
        aoff1[ph] = (uint32_t)(ar1 * 1024 + ((((2 * ph + ak8) & 7) ^ (ar1 & 7)) << 4));
        int br0 = brow_base, br1 = brow_base + 16;
        boff0[ph] = (uint32_t)(br0 * 256 + ((((2 * ph + bk8) & 7) ^ (br0 & 7)) << 4));
        boff1[ph] = (uint32_t)(br1 * 256 + ((((2 * ph + bk8) & 7) ^ (br1 & 7)) << 4));
    }

    // Precomputed cp.async per-thread offsets for B chunks (4 lines of 16B)
    uint32_t bdst[4], bsoff[4];
#pragma unroll
    for (int i = 0; i < 4; i++) {
        int f = tid + i * 512;
        int row = f >> 4, k = (f & 15) * 8;
        bdst[i]  = b_sw(row, k);
        bsoff[i] = (uint32_t)(row * KDIM + k);
    }

    const float alpha = g_scalars[1];
    const float2* e2 = (const float2*)g_enorm2;

    float bestv[4];
    int   besti[4];
    int   cur_m = -1;

    float acc[2][4][4];
#pragma unroll
    for (int a = 0; a < 2; a++)
#pragma unroll
        for (int b = 0; b < 4; b++)
#pragma unroll
            for (int d = 0; d < 4; d++) acc[a][b][d] = 0.0f;

    while (true) {
        __syncthreads();   // protects s_run reuse + As overwrite vs prior reads
        if (tid == 0) s_run = atomicAdd(&g_unit_ctr, 1u);
        __syncthreads();
        const unsigned run = s_run;
        if (run >= RUNS_TOTAL) break;

        const int m_tile = (int)(run >> 4);
        const int nbase  = (int)(run & 15u) * 1024;

        if (m_tile != cur_m) {
            if (cur_m >= 0) {
#pragma unroll
                for (int mt = 0; mt < 2; mt++)
#pragma unroll
                    for (int h = 0; h < 2; h++) {
                        int mloc = wm * 32 + mt * 16 + h * 8 + g;
                        atomicMin(&g_best[cur_m * 128 + mloc],
                                  pack_key(bestv[mt * 2 + h], (unsigned)besti[mt * 2 + h]));
                    }
            }
#pragma unroll
            for (int i = 0; i < 4; i++) { bestv[i] = 3.4e38f; besti[i] = 0; }
            cur_m = m_tile;
            const int m0 = m_tile * 128;
#pragma unroll
            for (int seg = 0; seg < 2; seg++) {
                const __nv_bfloat16* src = seg ? g_z_lo : g_z_hi;
                for (int f = tid; f < 4096; f += 512) {
                    int row = f >> 5, k = (f & 31) * 8;
                    cp_async16(As + a_sw(row, seg * 256 + k),
                               src + (size_t)(m0 + row) * KDIM + k);
                }
            }
            cp_commit();     // covered by first cp_wait below
        }

        // prologue: chunks 0 and 1 (e_hi, kbase 0 and 128)
        {
            const __nv_bfloat16* s0 = g_e_hi + (size_t)nbase * KDIM;
#pragma unroll
            for (int i = 0; i < 4; i++) cp_async16(Bbuf0 + bdst[i], s0 + bsoff[i]);
            cp_commit();
            const __nv_bfloat16* s1 = s0 + 128;
#pragma unroll
            for (int i = 0; i < 4; i++) cp_async16(Bbuf0 + SM_B_BYTES + bdst[i], s1 + bsoff[i]);
            cp_commit();
        }

#pragma unroll 1
        for (int c = 0; c < 32; c++) {
            if (c < 31) cp_wait<1>(); else cp_wait<0>();
            __syncthreads();
            if (c < 30) {
                const int cn = c + 2;
                const int s  = cn >> 2, p = cn & 3;
                const __nv_bfloat16* src = ((p < 2) ? g_e_hi : g_e_lo)
                    + (size_t)(nbase + s * 128) * KDIM + (p & 1) * 128;
                const uint32_t dst = Bbuf0 + (uint32_t)(cn % 3) * SM_B_BYTES;
#pragma unroll
                for (int i = 0; i < 4; i++) cp_async16(dst + bdst[i], src + bsoff[i]);
                cp_commit();
            }
            const int p = c & 3;
            const uint32_t abase2 = (uint32_t)((p & 1) * 256);
            const uint32_t Bb = Bbuf0 + (uint32_t)(c % 3) * SM_B_BYTES;
            if (p < 2)
                pass_t<true>(As, Bb, abase2, aoff0, aoff1, boff0, boff1, acc);
            else
                pass_t<false>(As, Bb, abase2, aoff0, aoff1, boff0, boff1, acc);

            if (p == 3) {
                const int n0 = nbase + (c >> 2) * 128;
#pragma unroll
                for (int mt = 0; mt < 2; mt++) {
#pragma unroll
                    for (int nt = 0; nt < 4; nt++) {
                        const int nloc = wn * 32 + nt * 8 + 2 * cc;
                        const int gn = n0 + nloc;
                        float2 ev = __ldg(e2 + ((unsigned)gn >> 1));
                        float v0 = fmaf(-alpha, acc[mt][nt][0], ev.x);
                        float v1 = fmaf(-alpha, acc[mt][nt][1], ev.y);
                        float v2 = fmaf(-alpha, acc[mt][nt][2], ev.x);
                        float v3 = fmaf(-alpha, acc[mt][nt][3], ev.y);
                        const int i0 = mt * 2, i1 = mt * 2 + 1;
                        if (v0 < bestv[i0]) { bestv[i0] = v0; besti[i0] = gn; }
                        if (v1 < bestv[i0]) { bestv[i0] = v1; besti[i0] = gn + 1; }
                        if (v2 < bestv[i1]) { bestv[i1] = v2; besti[i1] = gn; }
                        if (v3 < bestv[i1]) { bestv[i1] = v3; besti[i1] = gn + 1; }
                        acc[mt][nt][0] = 0.0f; acc[mt][nt][1] = 0.0f;
                        acc[mt][nt][2] = 0.0f; acc[mt][nt][3] = 0.0f;
                    }
                }
            }
        }
    }

    if (cur_m >= 0) {
#pragma unroll
        for (int mt = 0; mt < 2; mt++)
#pragma unroll
            for (int h = 0; h < 2; h++) {
                int mloc = wm * 32 + mt * 16 + h * 8 + g;
                atomicMin(&g_best[cur_m * 128 + mloc],
                          pack_key(bestv[mt * 2 + h], (unsigned)besti[mt * 2 + h]));
            }
    }
}

// ---------------- kernel 5 ----------------
__global__ void k_gather(const float* __restrict__ emb, float* __restrict__ out) {
    float scale = g_scalars[0];
    float lsum = 0.0f;
    for (int e = blockIdx.x * 256 + threadIdx.x; e < M_TOK * KDIM; e += 256 * 256) {
        int t = e >> 8;
        int c = e & 255;
        int idx = (int)(unsigned)(g_best[t] & 0xFFFFFFFFull);
        float zq = emb[(size_t)idx * KDIM + c] * FIXLEN;
        float zt = g_zflat[e] * scale;
        float d = zq - zt;
        lsum += d * d;
        int b  = t >> 10;
        int hw = t & 1023;
        out[(size_t)b * (KDIM * HWSZ) + (size_t)c * HWSZ + hw] = zq;
    }
    __shared__ float sred[256];
    sred[threadIdx.x] = lsum;
    __syncthreads();
    for (int s = 128; s > 0; s >>= 1) {
        if (threadIdx.x < s) sred[threadIdx.x] += sred[threadIdx.x + s];
        __syncthreads();
    }
    if (threadIdx.x == 0) g_diffpart[blockIdx.x] = sred[0];
}

// ---------------- kernel 6 ----------------
__global__ void k_final(float* __restrict__ out, int out_size) {
    __shared__ float s[256];
    s[threadIdx.x] = g_diffpart[threadIdx.x];
    __syncthreads();
    for (int st = 128; st > 0; st >>= 1) {
        if (threadIdx.x < st) s[threadIdx.x] += s[threadIdx.x + st];
        __syncthreads();
    }
    float diff = 0.25f * s[0] / (float)(M_TOK * KDIM);
    if (threadIdx.x == 0 && out_size > NZ) out[NZ] = diff;
    if (out_size >= NZ + 1 + M_TOK) {
        for (int t = threadIdx.x; t < M_TOK; t += 256)
            out[NZ + 1 + t] = (float)(unsigned)(g_best[t] & 0xFFFFFFFFull);
    }
}

// ---------------- launch ----------------
extern "C" void kernel_launch(void* const* d_in, const int* in_sizes, int n_in,
                              void* d_out, int out_size) {
    const float* z   = (const float*)d_in[0];
    const float* emb = (const float*)d_in[1];
    float* out = (float*)d_out;
    (void)in_sizes; (void)n_in;

    const int gemm_smem = 256 + SM_A_BYTES + 3 * SM_B_BYTES;  // 229,632 B
    cudaFuncSetAttribute(k_gemm_p, cudaFuncAttributeMaxDynamicSharedMemorySize, gemm_smem);

    k_prep<<<M_TOK / 256, 256>>>(z);
    k_scale<<<1, 64>>>();
    k_enorm<<<N_EMB / 8, 256>>>(emb);
    k_gemm_p<<<NUM_CTAS, 512, gemm_smem>>>();
    k_gather<<<256, 256>>>(emb, out);
    k_final<<<1, 256>>>(out, out_size);
}

// round 8
// speedup vs baseline: 1.0617x; 1.0617x over previous
#include <cuda_runtime.h>
#include <cuda_bf16.h>
#include <stdint.h>
#include <math.h>

#define M_TOK 16384
#define N_EMB 16384
#define KDIM  256
#define HWSZ  1024
#define NZ    (M_TOK * KDIM)
#define FIXLEN 30.0f

#define NUM_CTAS   152
#define RUNS_TOTAL 2048   /* 128 m-tiles x 16 runs; run = 8 n-subtiles of 128 */

// ---------------- device scratch (static, no allocation) ----------------
__device__ float          g_zflat[M_TOK * KDIM];
__device__ __nv_bfloat16  g_z_hi[M_TOK * KDIM];
__device__ __nv_bfloat16  g_z_lo[M_TOK * KDIM];
__device__ __nv_bfloat16  g_e_hi[N_EMB * KDIM];
__device__ __nv_bfloat16  g_e_lo[N_EMB * KDIM];
__device__ float          g_enorm2[N_EMB];
__device__ unsigned long long g_best[M_TOK];   // packed (ordered-float << 32) | idx
__device__ unsigned       g_unit_ctr;
__device__ float          g_normpart[512];
__device__ float          g_scalars[2];
__device__ float          g_diffpart[512];

// ---------------- small helpers ----------------
__device__ __forceinline__ uint32_t smem_u32(const void* p) {
    uint32_t a;
    asm("{ .reg .u64 t; cvta.to.shared.u64 t, %1; cvt.u32.u64 %0, t; }" : "=r"(a) : "l"(p));
    return a;
}
__device__ __forceinline__ void cp_async16(uint32_t dst, const void* src) {
    uint64_t g = __cvta_generic_to_global(src);
    asm volatile("cp.async.cg.shared.global [%0], [%1], 16;" :: "r"(dst), "l"(g));
}
__device__ __forceinline__ void cp_commit() { asm volatile("cp.async.commit_group;"); }
template <int N> __device__ __forceinline__ void cp_wait() {
    asm volatile("cp.async.wait_group %0;" :: "n"(N));
}
__device__ __forceinline__ void ldsm4(uint32_t* r, uint32_t addr) {
    asm volatile("ldmatrix.sync.aligned.m8n8.x4.shared.b16 {%0,%1,%2,%3}, [%4];"
                 : "=r"(r[0]), "=r"(r[1]), "=r"(r[2]), "=r"(r[3]) : "r"(addr));
}
__device__ __forceinline__ void mma16816(float* c, const uint32_t* a, uint32_t b0, uint32_t b1) {
    asm volatile("mma.sync.aligned.m16n8k16.row.col.f32.bf16.bf16.f32 "
                 "{%0,%1,%2,%3}, {%4,%5,%6,%7}, {%8,%9}, {%0,%1,%2,%3};"
                 : "+f"(c[0]), "+f"(c[1]), "+f"(c[2]), "+f"(c[3])
                 : "r"(a[0]), "r"(a[1]), "r"(a[2]), "r"(a[3]), "r"(b0), "r"(b1));
}
__device__ __forceinline__ unsigned long long pack_key(float v, unsigned idx) {
    unsigned u = __float_as_uint(v);
    u = (u & 0x80000000u) ? ~u : (u | 0x80000000u);
    return ((unsigned long long)u << 32) | idx;
}

__device__ __forceinline__ void split4(float4 v, uint2& ph, uint2& pl) {
    __nv_bfloat16 h0 = __float2bfloat16(v.x), h1 = __float2bfloat16(v.y),
                  h2 = __float2bfloat16(v.z), h3 = __float2bfloat16(v.w);
    __nv_bfloat16 l0 = __float2bfloat16(v.x - __bfloat162float(h0));
    __nv_bfloat16 l1 = __float2bfloat16(v.y - __bfloat162float(h1));
    __nv_bfloat16 l2 = __float2bfloat16(v.z - __bfloat162float(h2));
    __nv_bfloat16 l3 = __float2bfloat16(v.w - __bfloat162float(h3));
    ph.x = (uint32_t)__bfloat16_as_ushort(h0) | ((uint32_t)__bfloat16_as_ushort(h1) << 16);
    ph.y = (uint32_t)__bfloat16_as_ushort(h2) | ((uint32_t)__bfloat16_as_ushort(h3) << 16);
    pl.x = (uint32_t)__bfloat16_as_ushort(l0) | ((uint32_t)__bfloat16_as_ushort(l1) << 16);
    pl.y = (uint32_t)__bfloat16_as_ushort(l2) | ((uint32_t)__bfloat16_as_ushort(l3) << 16);
}

// ---------------- kernel 1: prep via 32-token transpose tile ----------------
// Block = 32 consecutive tokens (same b). Reads z coalesced along hw, writes
// zflat/hi/lo coalesced along c. 512 blocks x 256 threads.
__global__ void k_prep32(const float* __restrict__ z) {
    __shared__ float tile[32 * 257];
    __shared__ float pn[8][33];

    const int tid = threadIdx.x;
    const int tx  = tid & 31;    // hw offset
    const int ty  = tid >> 5;    // c-slice
    const int blk = blockIdx.x;
    const int b   = blk >> 5;
    const int hw0 = (blk & 31) * 32;

    const float* zp = z + (size_t)b * (KDIM * HWSZ) + hw0 + tx;
    float np = 0.0f;
#pragma unroll 8
    for (int cc = 0; cc < 32; cc++) {
        int c = ty * 32 + cc;
        float v = zp[(size_t)c * HWSZ];
        tile[tx * 257 + c] = v;
        np += v * v;
    }
    pn[ty][tx] = np;
    __syncthreads();
    if (tid < 32) {
        float s = 0.0f;
#pragma unroll
        for (int j = 0; j < 8; j++) s += pn[j][tid];
        pn[0][tid] = sqrtf(s);
        g_best[blk * 32 + tid] = 0xFFFFFFFFFFFFFFFFull;
    }
    __syncthreads();
    if (tid == 0) {
        float s = 0.0f;
#pragma unroll
        for (int i = 0; i < 32; i++) s += pn[0][i];
        g_normpart[blk] = s;
    }

    // write phase: thread owns channel c = tid for each of the 32 tokens
#pragma unroll 4
    for (int tok = 0; tok < 32; tok++) {
        const int t = blk * 32 + tok;
        float v = tile[tok * 257 + tid];
        g_zflat[t * KDIM + tid] = v;
        __nv_bfloat16 h = __float2bfloat16(v);
        __nv_bfloat16 l = __float2bfloat16(v - __bfloat162float(h));
        g_z_hi[t * KDIM + tid] = h;
        g_z_lo[t * KDIM + tid] = l;
    }
}

// ---------------- kernel 2: scale + counter reset ----------------
__global__ void k_scale() {
    __shared__ float s[512];
    s[threadIdx.x] = g_normpart[threadIdx.x];
    __syncthreads();
    for (int st = 256; st > 0; st >>= 1) {
        if (threadIdx.x < st) s[threadIdx.x] += s[threadIdx.x + st];
        __syncthreads();
    }
    if (threadIdx.x == 0) {
        float pre_len = s[0] / (float)M_TOK;
        float scale = (pre_len >= FIXLEN) ? (FIXLEN / pre_len) : 1.0f;
        g_scalars[0] = scale;
        g_scalars[1] = 2.0f * scale / FIXLEN;
        g_unit_ctr = 0u;
    }
}

// ---------------- kernel 3 ----------------
__global__ void k_enorm(const float* __restrict__ emb) {
    int w    = threadIdx.x >> 5;
    int lane = threadIdx.x & 31;
    int r    = blockIdx.x * 8 + w;
    const float4* ep = (const float4*)(emb + (size_t)r * KDIM);
    float4 a = ep[lane];
    float4 b = ep[lane + 32];
    float acc = a.x * a.x + a.y * a.y + a.z * a.z + a.w * a.w
              + b.x * b.x + b.y * b.y + b.z * b.z + b.w * b.w;
    uint2 ph, pl;
    split4(a, ph, pl);
    *(uint2*)&g_e_hi[(size_t)r * KDIM + 4 * lane] = ph;
    *(uint2*)&g_e_lo[(size_t)r * KDIM + 4 * lane] = pl;
    split4(b, ph, pl);
    *(uint2*)&g_e_hi[(size_t)r * KDIM + 128 + 4 * lane] = ph;
    *(uint2*)&g_e_lo[(size_t)r * KDIM + 128 + 4 * lane] = pl;
#pragma unroll
    for (int s = 16; s > 0; s >>= 1)
        acc += __shfl_down_sync(0xffffffffu, acc, s);
    if (lane == 0) g_enorm2[r] = acc;
}

// ---------------- kernel 4: persistent HMMA bf16x3 GEMM + fused argmin ----------------
#define SM_A_BYTES 131072
#define SM_B_BYTES 32768

__device__ __forceinline__ uint32_t a_sw(int row, int col) {   // col in [0,512)
    return (uint32_t)(row * 1024 + ((col >> 6) << 7)
           + (((((col >> 3) & 7) ^ (row & 7))) << 4) + ((col & 7) << 1));
}
__device__ __forceinline__ uint32_t b_sw(int row, int col) {   // col in [0,128)
    return (uint32_t)(row * 256 + ((col >> 6) << 7)
           + (((((col >> 3) & 7) ^ (row & 7))) << 4) + ((col & 7) << 1));
}

extern __shared__ char dsm[];

template <bool DUAL>
__device__ __forceinline__ void pass_t(
    uint32_t As, uint32_t Bb, uint32_t abase2,
    const uint32_t* aoff0, const uint32_t* aoff1,
    const uint32_t* boff0, const uint32_t* boff1,
    float acc[2][4][4])
{
    const uint32_t* aoff[2] = { aoff0, aoff1 };
    const uint32_t* boff[2] = { boff0, boff1 };
    uint32_t ah[2][2][4], al[2][2][4], br[2][2][4];
#pragma unroll
    for (int mt = 0; mt < 2; mt++) {
        ldsm4(ah[0][mt], As + aoff[mt][0] + abase2);
        if (DUAL) ldsm4(al[0][mt], As + aoff[mt][0] + abase2 + 512u);
    }
#pragma unroll
    for (int np = 0; np < 2; np++)
        ldsm4(br[0][np], Bb + boff[np][0]);
#pragma unroll
    for (int kk = 0; kk < 8; kk++) {
        const int cur = kk & 1, nxt = cur ^ 1;
        if (kk < 7) {
            const uint32_t hi = ((kk + 1) & 4) ? 128u : 0u;
            const int ph = (kk + 1) & 3;
#pragma unroll
            for (int mt = 0; mt < 2; mt++) {
                ldsm4(ah[nxt][mt], As + aoff[mt][ph] + hi + abase2);
                if (DUAL) ldsm4(al[nxt][mt], As + aoff[mt][ph] + hi + abase2 + 512u);
            }
#pragma unroll
            for (int np = 0; np < 2; np++)
                ldsm4(br[nxt][np], Bb + boff[np][ph] + hi);
        }
#pragma unroll
        for (int mt = 0; mt < 2; mt++)
#pragma unroll
            for (int nt = 0; nt < 4; nt++)
                mma16816(acc[mt][nt], ah[cur][mt],
                         br[cur][nt >> 1][(nt & 1) * 2], br[cur][nt >> 1][(nt & 1) * 2 + 1]);
        if (DUAL) {
#pragma unroll
            for (int mt = 0; mt < 2; mt++)
#pragma unroll
                for (int nt = 0; nt < 4; nt++)
                    mma16816(acc[mt][nt], al[cur][mt],
                             br[cur][nt >> 1][(nt & 1) * 2], br[cur][nt >> 1][(nt & 1) * 2 + 1]);
        }
    }
}

__global__ void __launch_bounds__(512, 1) k_gemm_p() {
    __shared__ unsigned s_run;

    const int tid  = threadIdx.x;
    const int lane = tid & 31;
    const int wid  = tid >> 5;
    const int wm   = wid & 3;
    const int wn   = wid >> 2;
    const int g    = lane >> 2;
    const int cc   = lane & 3;
    const int sub  = lane >> 3;
    const int r8   = lane & 7;

    uint32_t raw  = smem_u32(dsm);
    uint32_t base = (raw + 255u) & ~255u;
    const uint32_t As = base;
    const uint32_t Bbuf0 = base + SM_A_BYTES;

    const int arow_base = wm * 32 + ((sub & 1) << 3) + r8;
    const int ak8       = (sub >> 1) & 1;
    const int brow_base = wn * 32 + ((sub >> 1) << 3) + r8;
    const int bk8       = sub & 1;

    uint32_t aoff0[4], aoff1[4], boff0[4], boff1[4];
#pragma unroll
    for (int ph = 0; ph < 4; ph++) {
        int ar0 = arow_base, ar1 = arow_base + 16;
        aoff0[ph] = (uint32_t)(ar0 * 1024 + ((((2 * ph + ak8) & 7) ^ (ar0 & 7)) << 4));
        aoff1[ph] = (uint32_t)(ar1 * 1024 + ((((2 * ph + ak8) & 7) ^ (ar1 & 7)) << 4));
        int br0 = brow_base, br1 = brow_base + 16;
        boff0[ph] = (uint32_t)(br0 * 256 + ((((2 * ph + bk8) & 7) ^ (br0 & 7)) << 4));
        boff1[ph] = (uint32_t)(br1 * 256 + ((((2 * ph + bk8) & 7) ^ (br1 & 7)) << 4));
    }

    uint32_t bdst[4], bsoff[4];
#pragma unroll
    for (int i = 0; i < 4; i++) {
        int f = tid + i * 512;
        int row = f >> 4, k = (f & 15) * 8;
        bdst[i]  = b_sw(row, k);
        bsoff[i] = (uint32_t)(row * KDIM + k);
    }

    const float alpha = g_scalars[1];
    const float2* e2 = (const float2*)g_enorm2;

    float bestv[4];
    int   besti[4];
    int   cur_m = -1;

    float acc[2][4][4];
#pragma unroll
    for (int a = 0; a < 2; a++)
#pragma unroll
        for (int b = 0; b < 4; b++)
#pragma unroll
            for (int d = 0; d < 4; d++) acc[a][b][d] = 0.0f;

    while (true) {
        __syncthreads();
        if (tid == 0) s_run = atomicAdd(&g_unit_ctr, 1u);
        __syncthreads();
        const unsigned run = s_run;
        if (run >= RUNS_TOTAL) break;

        const int m_tile = (int)(run >> 4);
        const int nbase  = (int)(run & 15u) * 1024;

        if (m_tile != cur_m) {
            if (cur_m >= 0) {
#pragma unroll
                for (int mt = 0; mt < 2; mt++)
#pragma unroll
                    for (int h = 0; h < 2; h++) {
                        int mloc = wm * 32 + mt * 16 + h * 8 + g;
                        atomicMin(&g_best[cur_m * 128 + mloc],
                                  pack_key(bestv[mt * 2 + h], (unsigned)besti[mt * 2 + h]));
                    }
            }
#pragma unroll
            for (int i = 0; i < 4; i++) { bestv[i] = 3.4e38f; besti[i] = 0; }
            cur_m = m_tile;
            const int m0 = m_tile * 128;
#pragma unroll
            for (int seg = 0; seg < 2; seg++) {
                const __nv_bfloat16* src = seg ? g_z_lo : g_z_hi;
                for (int f = tid; f < 4096; f += 512) {
                    int row = f >> 5, k = (f & 31) * 8;
                    cp_async16(As + a_sw(row, seg * 256 + k),
                               src + (size_t)(m0 + row) * KDIM + k);
                }
            }
            cp_commit();
        }

        {
            const __nv_bfloat16* s0 = g_e_hi + (size_t)nbase * KDIM;
#pragma unroll
            for (int i = 0; i < 4; i++) cp_async16(Bbuf0 + bdst[i], s0 + bsoff[i]);
            cp_commit();
            const __nv_bfloat16* s1 = s0 + 128;
#pragma unroll
            for (int i = 0; i < 4; i++) cp_async16(Bbuf0 + SM_B_BYTES + bdst[i], s1 + bsoff[i]);
            cp_commit();
        }

#pragma unroll 1
        for (int c = 0; c < 32; c++) {
            if (c < 31) cp_wait<1>(); else cp_wait<0>();
            __syncthreads();
            if (c < 30) {
                const int cn = c + 2;
                const int s  = cn >> 2, p = cn & 3;
                const __nv_bfloat16* src = ((p < 2) ? g_e_hi : g_e_lo)
                    + (size_t)(nbase + s * 128) * KDIM + (p & 1) * 128;
                const uint32_t dst = Bbuf0 + (uint32_t)(cn % 3) * SM_B_BYTES;
#pragma unroll
                for (int i = 0; i < 4; i++) cp_async16(dst + bdst[i], src + bsoff[i]);
                cp_commit();
            }
            const int p = c & 3;
            const uint32_t abase2 = (uint32_t)((p & 1) * 256);
            const uint32_t Bb = Bbuf0 + (uint32_t)(c % 3) * SM_B_BYTES;
            if (p < 2)
                pass_t<true>(As, Bb, abase2, aoff0, aoff1, boff0, boff1, acc);
            else
                pass_t<false>(As, Bb, abase2, aoff0, aoff1, boff0, boff1, acc);

            if (p == 3) {
                const int n0 = nbase + (c >> 2) * 128;
#pragma unroll
                for (int mt = 0; mt < 2; mt++) {
#pragma unroll
                    for (int nt = 0; nt < 4; nt++) {
                        const int nloc = wn * 32 + nt * 8 + 2 * cc;
                        const int gn = n0 + nloc;
                        float2 ev = __ldg(e2 + ((unsigned)gn >> 1));
                        float v0 = fmaf(-alpha, acc[mt][nt][0], ev.x);
                        float v1 = fmaf(-alpha, acc[mt][nt][1], ev.y);
                        float v2 = fmaf(-alpha, acc[mt][nt][2], ev.x);
                        float v3 = fmaf(-alpha, acc[mt][nt][3], ev.y);
                        const int i0 = mt * 2, i1 = mt * 2 + 1;
                        if (v0 < bestv[i0]) { bestv[i0] = v0; besti[i0] = gn; }
                        if (v1 < bestv[i0]) { bestv[i0] = v1; besti[i0] = gn + 1; }
                        if (v2 < bestv[i1]) { bestv[i1] = v2; besti[i1] = gn; }
                        if (v3 < bestv[i1]) { bestv[i1] = v3; besti[i1] = gn + 1; }
                        acc[mt][nt][0] = 0.0f; acc[mt][nt][1] = 0.0f;
                        acc[mt][nt][2] = 0.0f; acc[mt][nt][3] = 0.0f;
                    }
                }
            }
        }
    }

    if (cur_m >= 0) {
#pragma unroll
        for (int mt = 0; mt < 2; mt++)
#pragma unroll
            for (int h = 0; h < 2; h++) {
                int mloc = wm * 32 + mt * 16 + h * 8 + g;
                atomicMin(&g_best[cur_m * 128 + mloc],
                          pack_key(bestv[mt * 2 + h], (unsigned)besti[mt * 2 + h]));
            }
    }
}

// ---------------- kernel 5: gather via 32-token transpose tile ----------------
__global__ void k_gather32(const float* __restrict__ emb, float* __restrict__ out) {
    __shared__ float tile[32 * 257];
    __shared__ float sred[256];

    const int tid = threadIdx.x;
    const int blk = blockIdx.x;
    const int b   = blk >> 5;
    const int hw0 = (blk & 31) * 32;

    const float scale = g_scalars[0];
    float lsum = 0.0f;

#pragma unroll 4
    for (int tok = 0; tok < 32; tok++) {
        const int t = blk * 32 + tok;
        const int idx = (int)(unsigned)(g_best[t] & 0xFFFFFFFFull);
        float zq = emb[(size_t)idx * KDIM + tid] * FIXLEN;
        float zt = g_zflat[t * KDIM + tid] * scale;
        float d = zq - zt;
        lsum += d * d;
        tile[tok * 257 + tid] = zq;
    }
    __syncthreads();

    // coalesced writes along hw
    const int tx = tid & 31;
    const int ty = tid >> 5;
    float* op = out + (size_t)b * (KDIM * HWSZ) + hw0 + tx;
#pragma unroll 8
    for (int ccc = 0; ccc < 32; ccc++) {
        int c = ty * 32 + ccc;
        op[(size_t)c * HWSZ] = tile[tx * 257 + c];
    }

    sred[tid] = lsum;
    __syncthreads();
    for (int s = 128; s > 0; s >>= 1) {
        if (tid < s) sred[tid] += sred[tid + s];
        __syncthreads();
    }
    if (tid == 0) g_diffpart[blk] = sred[0];
}

// ---------------- kernel 6 ----------------
__global__ void k_final(float* __restrict__ out, int out_size) {
    __shared__ float s[512];
    s[threadIdx.x] = g_diffpart[threadIdx.x];
    __syncthreads();
    for (int st = 256; st > 0; st >>= 1) {
        if (threadIdx.x < st) s[threadIdx.x] += s[threadIdx.x + st];
        __syncthreads();
    }
    float diff = 0.25f * s[0] / (float)(M_TOK * KDIM);
    if (threadIdx.x == 0 && out_size > NZ) out[NZ] = diff;
    if (out_size >= NZ + 1 + M_TOK) {
        for (int t = threadIdx.x; t < M_TOK; t += 512)
            out[NZ + 1 + t] = (float)(unsigned)(g_best[t] & 0xFFFFFFFFull);
    }
}

// ---------------- launch ----------------
extern "C" void kernel_launch(void* const* d_in, const int* in_sizes, int n_in,
                              void* d_out, int out_size) {
    const float* z   = (const float*)d_in[0];
    const float* emb = (const float*)d_in[1];
    float* out = (float*)d_out;
    (void)in_sizes; (void)n_in;

    const int gemm_smem = 256 + SM_A_BYTES + 3 * SM_B_BYTES;  // 229,632 B
    cudaFuncSetAttribute(k_gemm_p, cudaFuncAttributeMaxDynamicSharedMemorySize, gemm_smem);

    k_prep32<<<512, 256>>>(z);
    k_scale<<<1, 512>>>();
    k_enorm<<<N_EMB / 8, 256>>>(emb);
    k_gemm_p<<<NUM_CTAS, 512, gemm_smem>>>();
    k_gather32<<<512, 256>>>(emb, out);
    k_final<<<1, 512>>>(out, out_size);
}

// round 10
// speedup vs baseline: 1.1229x; 1.0577x over previous
#include <cuda_runtime.h>
#include <cuda_bf16.h>
#include <stdint.h>
#include <math.h>

#define M_TOK 16384
#define N_EMB 16384
#define KDIM  256
#define HWSZ  1024
#define NZ    (M_TOK * KDIM)
#define FIXLEN 30.0f

#define NUM_CTAS   304    /* 2 CTAs per SM x 152 SMs */
#define RUNS_TOTAL 4096   /* 256 m-tiles (64 tok) x 16 n-runs (1024 emb) */

// ---------------- device scratch (static, no allocation) ----------------
__device__ float          g_zflat[M_TOK * KDIM];
__device__ __nv_bfloat16  g_z_hi[M_TOK * KDIM];
__device__ __nv_bfloat16  g_z_lo[M_TOK * KDIM];
__device__ __nv_bfloat16  g_e_hi[N_EMB * KDIM];
__device__ __nv_bfloat16  g_e_lo[N_EMB * KDIM];
__device__ float          g_enorm2[N_EMB];
__device__ unsigned long long g_best[M_TOK];   // packed (ordered-float << 32) | idx
__device__ unsigned       g_unit_ctr;
__device__ float          g_normpart[512];
__device__ float          g_scalars[2];
__device__ float          g_diffpart[512];

// ---------------- small helpers ----------------
__device__ __forceinline__ uint32_t smem_u32(const void* p) {
    uint32_t a;
    asm("{ .reg .u64 t; cvta.to.shared.u64 t, %1; cvt.u32.u64 %0, t; }" : "=r"(a) : "l"(p));
    return a;
}
__device__ __forceinline__ void cp_async16(uint32_t dst, const void* src) {
    uint64_t g = __cvta_generic_to_global(src);
    asm volatile("cp.async.cg.shared.global [%0], [%1], 16;" :: "r"(dst), "l"(g));
}
__device__ __forceinline__ void cp_commit() { asm volatile("cp.async.commit_group;"); }
template <int N> __device__ __forceinline__ void cp_wait() {
    asm volatile("cp.async.wait_group %0;" :: "n"(N));
}
__device__ __forceinline__ void ldsm4(uint32_t* r, uint32_t addr) {
    asm volatile("ldmatrix.sync.aligned.m8n8.x4.shared.b16 {%0,%1,%2,%3}, [%4];"
                 : "=r"(r[0]), "=r"(r[1]), "=r"(r[2]), "=r"(r[3]) : "r"(addr));
}
__device__ __forceinline__ void mma16816(float* c, const uint32_t* a, uint32_t b0, uint32_t b1) {
    asm volatile("mma.sync.aligned.m16n8k16.row.col.f32.bf16.bf16.f32 "
                 "{%0,%1,%2,%3}, {%4,%5,%6,%7}, {%8,%9}, {%0,%1,%2,%3};"
                 : "+f"(c[0]), "+f"(c[1]), "+f"(c[2]), "+f"(c[3])
                 : "r"(a[0]), "r"(a[1]), "r"(a[2]), "r"(a[3]), "r"(b0), "r"(b1));
}
__device__ __forceinline__ unsigned long long pack_key(float v, unsigned idx) {
    unsigned u = __float_as_uint(v);
    u = (u & 0x80000000u) ? ~u : (u | 0x80000000u);
    return ((unsigned long long)u << 32) | idx;
}

__device__ __forceinline__ void split4(float4 v, uint2& ph, uint2& pl) {
    __nv_bfloat16 h0 = __float2bfloat16(v.x), h1 = __float2bfloat16(v.y),
                  h2 = __float2bfloat16(v.z), h3 = __float2bfloat16(v.w);
    __nv_bfloat16 l0 = __float2bfloat16(v.x - __bfloat162float(h0));
    __nv_bfloat16 l1 = __float2bfloat16(v.y - __bfloat162float(h1));
    __nv_bfloat16 l2 = __float2bfloat16(v.z - __bfloat162float(h2));
    __nv_bfloat16 l3 = __float2bfloat16(v.w - __bfloat162float(h3));
    ph.x = (uint32_t)__bfloat16_as_ushort(h0) | ((uint32_t)__bfloat16_as_ushort(h1) << 16);
    ph.y = (uint32_t)__bfloat16_as_ushort(h2) | ((uint32_t)__bfloat16_as_ushort(h3) << 16);
    pl.x = (uint32_t)__bfloat16_as_ushort(l0) | ((uint32_t)__bfloat16_as_ushort(l1) << 16);
    pl.y = (uint32_t)__bfloat16_as_ushort(l2) | ((uint32_t)__bfloat16_as_ushort(l3) << 16);
}

// ---------------- kernel 1: prep via 32-token transpose tile ----------------
__global__ void k_prep32(const float* __restrict__ z) {
    __shared__ float tile[32 * 257];
    __shared__ float pn[8][33];

    const int tid = threadIdx.x;
    const int tx  = tid & 31;
    const int ty  = tid >> 5;
    const int blk = blockIdx.x;
    const int b   = blk >> 5;
    const int hw0 = (blk & 31) * 32;

    const float* zp = z + (size_t)b * (KDIM * HWSZ) + hw0 + tx;
    float np = 0.0f;
#pragma unroll 8
    for (int cc = 0; cc < 32; cc++) {
        int c = ty * 32 + cc;
        float v = zp[(size_t)c * HWSZ];
        tile[tx * 257 + c] = v;
        np += v * v;
    }
    pn[ty][tx] = np;
    __syncthreads();
    if (tid < 32) {
        float s = 0.0f;
#pragma unroll
        for (int j = 0; j < 8; j++) s += pn[j][tid];
        pn[0][tid] = sqrtf(s);
        g_best[blk * 32 + tid] = 0xFFFFFFFFFFFFFFFFull;
    }
    __syncthreads();
    if (tid == 0) {
        float s = 0.0f;
#pragma unroll
        for (int i = 0; i < 32; i++) s += pn[0][i];
        g_normpart[blk] = s;
    }

#pragma unroll 4
    for (int tok = 0; tok < 32; tok++) {
        const int t = blk * 32 + tok;
        float v = tile[tok * 257 + tid];
        g_zflat[t * KDIM + tid] = v;
        __nv_bfloat16 h = __float2bfloat16(v);
        __nv_bfloat16 l = __float2bfloat16(v - __bfloat162float(h));
        g_z_hi[t * KDIM + tid] = h;
        g_z_lo[t * KDIM + tid] = l;
    }
}

// ---------------- kernel 2: scale + counter reset ----------------
__global__ void k_scale() {
    __shared__ float s[512];
    s[threadIdx.x] = g_normpart[threadIdx.x];
    __syncthreads();
    for (int st = 256; st > 0; st >>= 1) {
        if (threadIdx.x < st) s[threadIdx.x] += s[threadIdx.x + st];
        __syncthreads();
    }
    if (threadIdx.x == 0) {
        float pre_len = s[0] / (float)M_TOK;
        float scale = (pre_len >= FIXLEN) ? (FIXLEN / pre_len) : 1.0f;
        g_scalars[0] = scale;
        g_scalars[1] = 2.0f * scale / FIXLEN;
        g_unit_ctr = 0u;
    }
}

// ---------------- kernel 3 ----------------
__global__ void k_enorm(const float* __restrict__ emb) {
    int w    = threadIdx.x >> 5;
    int lane = threadIdx.x & 31;
    int r    = blockIdx.x * 8 + w;
    const float4* ep = (const float4*)(emb + (size_t)r * KDIM);
    float4 a = ep[lane];
    float4 b = ep[lane + 32];
    float acc = a.x * a.x + a.y * a.y + a.z * a.z + a.w * a.w
              + b.x * b.x + b.y * b.y + b.z * b.z + b.w * b.w;
    uint2 ph, pl;
    split4(a, ph, pl);
    *(uint2*)&g_e_hi[(size_t)r * KDIM + 4 * lane] = ph;
    *(uint2*)&g_e_lo[(size_t)r * KDIM + 4 * lane] = pl;
    split4(b, ph, pl);
    *(uint2*)&g_e_hi[(size_t)r * KDIM + 128 + 4 * lane] = ph;
    *(uint2*)&g_e_lo[(size_t)r * KDIM + 128 + 4 * lane] = pl;
#pragma unroll
    for (int s = 16; s > 0; s >>= 1)
        acc += __shfl_down_sync(0xffffffffu, acc, s);
    if (lane == 0) g_enorm2[r] = acc;
}

// ---------------- kernel 4: persistent HMMA bf16x3, 2 CTAs/SM ----------------
// CTA = 256 threads (8 warps, 2m x 4n, warp tile 32x32), m-tile 64 tokens.
// A (64 x [hi|lo] 512 cols bf16) = 64KB; B chunks 128n x 64k = 16KB, 3 buffers.
// Per n-subtile: 8 chunks (4 e_hi dual-pass a_hi+a_lo, 4 e_lo single-pass a_hi).
#define SM_A_BYTES 65536
#define SM_B_BYTES 16384

__device__ __forceinline__ uint32_t a_sw(int row, int col) {   // col in [0,512)
    return (uint32_t)(row * 1024 + ((col >> 6) << 7)
           + (((((col >> 3) & 7) ^ (row & 7))) << 4) + ((col & 7) << 1));
}
__device__ __forceinline__ uint32_t b_sw64(int row, int col) { // col in [0,64)
    return (uint32_t)(row * 128 + ((((col >> 3) ^ (row & 7))) << 4) + ((col & 7) << 1));
}

extern __shared__ char dsm[];

// 4 k16-steps over one 64k-wide B chunk. DUAL: also multiply the a_lo block
// (at +512 bytes = cols 256..). ablk = byte offset of the A 64-col hi block.
template <bool DUAL>
__device__ __forceinline__ void pass4(
    uint32_t As, uint32_t Bb, uint32_t ablk,
    const uint32_t* aoff0, const uint32_t* aoff1,
    const uint32_t* boff0, const uint32_t* boff1,
    float acc[2][4][4])
{
    const uint32_t* aoff[2] = { aoff0, aoff1 };
    const uint32_t* boff[2] = { boff0, boff1 };
    uint32_t ah[2][2][4], al[2][2][4], br[2][2][4];
#pragma unroll
    for (int mt = 0; mt < 2; mt++) {
        ldsm4(ah[0][mt], As + aoff[mt][0] + ablk);
        if (DUAL) ldsm4(al[0][mt], As + aoff[mt][0] + ablk + 512u);
    }
#pragma unroll
    for (int np = 0; np < 2; np++)
        ldsm4(br[0][np], Bb + boff[np][0]);
#pragma unroll
    for (int kk = 0; kk < 4; kk++) {
        const int cur = kk & 1, nxt = cur ^ 1;
        if (kk < 3) {
            const int ph = kk + 1;
#pragma unroll
            for (int mt = 0; mt < 2; mt++) {
                ldsm4(ah[nxt][mt], As + aoff[mt][ph] + ablk);
                if (DUAL) ldsm4(al[nxt][mt], As + aoff[mt][ph] + ablk + 512u);
            }
#pragma unroll
            for (int np = 0; np < 2; np++)
                ldsm4(br[nxt][np], Bb + boff[np][ph]);
        }
#pragma unroll
        for (int mt = 0; mt < 2; mt++)
#pragma unroll
            for (int nt = 0; nt < 4; nt++)
                mma16816(acc[mt][nt], ah[cur][mt],
                         br[cur][nt >> 1][(nt & 1) * 2], br[cur][nt >> 1][(nt & 1) * 2 + 1]);
        if (DUAL) {
#pragma unroll
            for (int mt = 0; mt < 2; mt++)
#pragma unroll
                for (int nt = 0; nt < 4; nt++)
                    mma16816(acc[mt][nt], al[cur][mt],
                             br[cur][nt >> 1][(nt & 1) * 2], br[cur][nt >> 1][(nt & 1) * 2 + 1]);
        }
    }
}

__global__ void __launch_bounds__(256, 2) k_gemm_p() {
    __shared__ unsigned s_run;

    const int tid  = threadIdx.x;
    const int lane = tid & 31;
    const int wid  = tid >> 5;
    const int wm   = wid & 1;        // 2 warps along m
    const int wn   = wid >> 1;       // 4 warps along n
    const int g    = lane >> 2;
    const int cc   = lane & 3;
    const int sub  = lane >> 3;
    const int r8   = lane & 7;

    uint32_t raw  = smem_u32(dsm);
    uint32_t base = (raw + 255u) & ~255u;
    const uint32_t As = base;
    const uint32_t Bbuf0 = base + SM_A_BYTES;

    const int arow_base = wm * 32 + ((sub & 1) << 3) + r8;   // < 64
    const int ak8       = (sub >> 1) & 1;
    const int brow_base = wn * 32 + ((sub >> 1) << 3) + r8;  // < 128
    const int bk8       = sub & 1;

    uint32_t aoff0[4], aoff1[4], boff0[4], boff1[4];
#pragma unroll
    for (int ph = 0; ph < 4; ph++) {
        int ar0 = arow_base, ar1 = arow_base + 16;
        aoff0[ph] = (uint32_t)(ar0 * 1024 + ((((2 * ph + ak8) & 7) ^ (ar0 & 7)) << 4));
        aoff1[ph] = (uint32_t)(ar1 * 1024 + ((((2 * ph + ak8) & 7) ^ (ar1 & 7)) << 4));
        int br0 = brow_base, br1 = brow_base + 16;
        boff0[ph] = (uint32_t)(br0 * 128 + ((((2 * ph + bk8) & 7) ^ (br0 & 7)) << 4));
        boff1[ph] = (uint32_t)(br1 * 128 + ((((2 * ph + bk8) & 7) ^ (br1 & 7)) << 4));
    }

    uint32_t bdst[4], bsoff[4];
#pragma unroll
    for (int i = 0; i < 4; i++) {
        int f = tid + i * 256;
        int row = f >> 3, k = (f & 7) * 8;
        bdst[i]  = b_sw64(row, k);
        bsoff[i] = (uint32_t)(row * KDIM + k);
    }

    const float alpha = g_scalars[1];
    const float2* e2 = (const float2*)g_enorm2;

    float bestv[4];
    int   besti[4];
    int   cur_m = -1;

    float acc[2][4][4];
#pragma unroll
    for (int a = 0; a < 2; a++)
#pragma unroll
        for (int b = 0; b < 4; b++)
#pragma unroll
            for (int d = 0; d < 4; d++) acc[a][b][d] = 0.0f;

    while (true) {
        __syncthreads();
        if (tid == 0) s_run = atomicAdd(&g_unit_ctr, 1u);
        __syncthreads();
        const unsigned run = s_run;
        if (run >= RUNS_TOTAL) break;

        const int m_tile = (int)(run >> 4);          // 0..255 (64 tokens each)
        const int nbase  = (int)(run & 15u) * 1024;

        if (m_tile != cur_m) {
            if (cur_m >= 0) {
#pragma unroll
                for (int mt = 0; mt < 2; mt++)
#pragma unroll
                    for (int h = 0; h < 2; h++) {
                        int mloc = wm * 32 + mt * 16 + h * 8 + g;
                        atomicMin(&g_best[cur_m * 64 + mloc],
                                  pack_key(bestv[mt * 2 + h], (unsigned)besti[mt * 2 + h]));
                    }
            }
#pragma unroll
            for (int i = 0; i < 4; i++) { bestv[i] = 3.4e38f; besti[i] = 0; }
            cur_m = m_tile;
            const int m0 = m_tile * 64;
#pragma unroll
            for (int seg = 0; seg < 2; seg++) {
                const __nv_bfloat16* src = seg ? g_z_lo : g_z_hi;
                for (int f = tid; f < 2048; f += 256) {
                    int row = f >> 5, k = (f & 31) * 8;
                    cp_async16(As + a_sw(row, seg * 256 + k),
                               src + (size_t)(m0 + row) * KDIM + k);
                }
            }
            cp_commit();
        }

        // prologue: chunks 0 (e_hi k0) and 1 (e_hi k64) of subtile 0
        {
            const __nv_bfloat16* s0 = g_e_hi + (size_t)nbase * KDIM;
#pragma unroll
            for (int i = 0; i < 4; i++) cp_async16(Bbuf0 + bdst[i], s0 + bsoff[i]);
            cp_commit();
            const __nv_bfloat16* s1 = s0 + 64;
#pragma unroll
            for (int i = 0; i < 4; i++) cp_async16(Bbuf0 + SM_B_BYTES + bdst[i], s1 + bsoff[i]);
            cp_commit();
        }

#pragma unroll 1
        for (int c = 0; c < 64; c++) {
            if (c < 63) cp_wait<1>(); else cp_wait<0>();
            __syncthreads();
            if (c < 62) {
                const int cn = c + 2;
                const int s  = cn >> 3, p = cn & 7;
                const __nv_bfloat16* src = ((p < 4) ? g_e_hi : g_e_lo)
                    + (size_t)(nbase + s * 128) * KDIM + (p & 3) * 64;
                const uint32_t dst = Bbuf0 + (uint32_t)(cn % 3) * SM_B_BYTES;
#pragma unroll
                for (int i = 0; i < 4; i++) cp_async16(dst + bdst[i], src + bsoff[i]);
                cp_commit();
            }
            const int p = c & 7;
            const uint32_t Bb = Bbuf0 + (uint32_t)(c % 3) * SM_B_BYTES;
            // FIX (round 9 bug): e_lo chunks multiply the a_HI block at
            // (p-4)*128 — NOT the a_lo block (+512). Term set restored to
            // a_hi*b_hi + a_lo*b_hi + a_hi*b_lo.
            if (p < 4) {
                const uint32_t ablk = (uint32_t)(p * 128);
                pass4<true>(As, Bb, ablk, aoff0, aoff1, boff0, boff1, acc);
            } else {
                const uint32_t ablk = (uint32_t)((p - 4) * 128);
                pass4<false>(As, Bb, ablk, aoff0, aoff1, boff0, boff1, acc);
            }

            if (p == 7) {
                const int n0 = nbase + (c >> 3) * 128;
#pragma unroll
                for (int mt = 0; mt < 2; mt++) {
#pragma unroll
                    for (int nt = 0; nt < 4; nt++) {
                        const int nloc = wn * 32 + nt * 8 + 2 * cc;
                        const int gn = n0 + nloc;
                        float2 ev = __ldg(e2 + ((unsigned)gn >> 1));
                        float v0 = fmaf(-alpha, acc[mt][nt][0], ev.x);
                        float v1 = fmaf(-alpha, acc[mt][nt][1], ev.y);
                        float v2 = fmaf(-alpha, acc[mt][nt][2], ev.x);
                        float v3 = fmaf(-alpha, acc[mt][nt][3], ev.y);
                        const int i0 = mt * 2, i1 = mt * 2 + 1;
                        if (v0 < bestv[i0]) { bestv[i0] = v0; besti[i0] = gn; }
                        if (v1 < bestv[i0]) { bestv[i0] = v1; besti[i0] = gn + 1; }
                        if (v2 < bestv[i1]) { bestv[i1] = v2; besti[i1] = gn; }
                        if (v3 < bestv[i1]) { bestv[i1] = v3; besti[i1] = gn + 1; }
                        acc[mt][nt][0] = 0.0f; acc[mt][nt][1] = 0.0f;
                        acc[mt][nt][2] = 0.0f; acc[mt][nt][3] = 0.0f;
                    }
                }
            }
        }
    }

    if (cur_m >= 0) {
#pragma unroll
        for (int mt = 0; mt < 2; mt++)
#pragma unroll
            for (int h = 0; h < 2; h++) {
                int mloc = wm * 32 + mt * 16 + h * 8 + g;
                atomicMin(&g_best[cur_m * 64 + mloc],
                          pack_key(bestv[mt * 2 + h], (unsigned)besti[mt * 2 + h]));
            }
    }
}

// ---------------- kernel 5: gather via 32-token transpose tile ----------------
__global__ void k_gather32(const float* __restrict__ emb, float* __restrict__ out) {
    __shared__ float tile[32 * 257];
    __shared__ float sred[256];

    const int tid = threadIdx.x;
    const int blk = blockIdx.x;
    const int b   = blk >> 5;
    const int hw0 = (blk & 31) * 32;

    const float scale = g_scalars[0];
    float lsum = 0.0f;

#pragma unroll 4
    for (int tok = 0; tok < 32; tok++) {
        const int t = blk * 32 + tok;
        const int idx = (int)(unsigned)(g_best[t] & 0xFFFFFFFFull);
        float zq = emb[(size_t)idx * KDIM + tid] * FIXLEN;
        float zt = g_zflat[t * KDIM + tid] * scale;
        float d = zq - zt;
        lsum += d * d;
        tile[tok * 257 + tid] = zq;
    }
    __syncthreads();

    const int tx = tid & 31;
    const int ty = tid >> 5;
    float* op = out + (size_t)b * (KDIM * HWSZ) + hw0 + tx;
#pragma unroll 8
    for (int ccc = 0; ccc < 32; ccc++) {
        int c = ty * 32 + ccc;
        op[(size_t)c * HWSZ] = tile[tx * 257 + c];
    }

    sred[tid] = lsum;
    __syncthreads();
    for (int s = 128; s > 0; s >>= 1) {
        if (tid < s) sred[tid] += sred[tid + s];
        __syncthreads();
    }
    if (tid == 0) g_diffpart[blk] = sred[0];
}

// ---------------- kernel 6 ----------------
__global__ void k_final(float* __restrict__ out, int out_size) {
    __shared__ float s[512];
    s[threadIdx.x] = g_diffpart[threadIdx.x];
    __syncthreads();
    for (int st = 256; st > 0; st >>= 1) {
        if (threadIdx.x < st) s[threadIdx.x] += s[threadIdx.x + st];
        __syncthreads();
    }
    float diff = 0.25f * s[0] / (float)(M_TOK * KDIM);
    if (threadIdx.x == 0 && out_size > NZ) out[NZ] = diff;
    if (out_size >= NZ + 1 + M_TOK) {
        for (int t = threadIdx.x; t < M_TOK; t += 512)
            out[NZ + 1 + t] = (float)(unsigned)(g_best[t] & 0xFFFFFFFFull);
    }
}

// ---------------- launch ----------------
extern "C" void kernel_launch(void* const* d_in, const int* in_sizes, int n_in,
                              void* d_out, int out_size) {
    const float* z   = (const float*)d_in[0];
    const float* emb = (const float*)d_in[1];
    float* out = (float*)d_out;
    (void)in_sizes; (void)n_in;

    const int gemm_smem = 256 + SM_A_BYTES + 3 * SM_B_BYTES;  // 114,944 B/CTA
    cudaFuncSetAttribute(k_gemm_p, cudaFuncAttributeMaxDynamicSharedMemorySize, gemm_smem);

    k_prep32<<<512, 256>>>(z);
    k_scale<<<1, 512>>>();
    k_enorm<<<N_EMB / 8, 256>>>(emb);
    k_gemm_p<<<NUM_CTAS, 256, gemm_smem>>>();
    k_gather32<<<512, 256>>>(emb, out);
    k_final<<<1, 512>>>(out, out_size);
}

// round 11
// speedup vs baseline: 1.2198x; 1.0863x over previous
#include <cuda_runtime.h>
#include <cuda_bf16.h>
#include <stdint.h>
#include <math.h>

#define M_TOK 16384
#define N_EMB 16384
#define KDIM  256
#define HWSZ  1024
#define NZ    (M_TOK * KDIM)
#define FIXLEN 30.0f

#define NUM_CTAS   304    /* 2 CTAs per SM x 152 SMs */
#define RUNS_TOTAL 2048   /* 256 m-tiles (64 tok) x 8 n-halves (2048 emb) */

// ---------------- device scratch (static, no allocation) ----------------
__device__ float          g_zflat[M_TOK * KDIM];
__device__ __nv_bfloat16  g_z_hi[M_TOK * KDIM];
__device__ __nv_bfloat16  g_z_lo[M_TOK * KDIM];
__device__ __nv_bfloat16  g_e_hi[N_EMB * KDIM];
__device__ __nv_bfloat16  g_e_lo[N_EMB * KDIM];
__device__ float          g_enorm2[N_EMB];
__device__ unsigned long long g_best[M_TOK];   // packed (ordered-float << 32) | idx
__device__ unsigned       g_unit_ctr;
__device__ float          g_normpart[512];
__device__ float          g_scalars[2];
__device__ float          g_diffpart[512];

// ---------------- small helpers ----------------
__device__ __forceinline__ uint32_t smem_u32(const void* p) {
    uint32_t a;
    asm("{ .reg .u64 t; cvta.to.shared.u64 t, %1; cvt.u32.u64 %0, t; }" : "=r"(a) : "l"(p));
    return a;
}
__device__ __forceinline__ void cp_async16(uint32_t dst, const void* src) {
    uint64_t g = __cvta_generic_to_global(src);
    asm volatile("cp.async.cg.shared.global [%0], [%1], 16;" :: "r"(dst), "l"(g));
}
__device__ __forceinline__ void cp_commit() { asm volatile("cp.async.commit_group;"); }
template <int N> __device__ __forceinline__ void cp_wait() {
    asm volatile("cp.async.wait_group %0;" :: "n"(N));
}
__device__ __forceinline__ void bar_pair(int id) {
    asm volatile("bar.sync %0, 64;" :: "r"(id) : "memory");
}
__device__ __forceinline__ void ldsm4(uint32_t* r, uint32_t addr) {
    asm volatile("ldmatrix.sync.aligned.m8n8.x4.shared.b16 {%0,%1,%2,%3}, [%4];"
                 : "=r"(r[0]), "=r"(r[1]), "=r"(r[2]), "=r"(r[3]) : "r"(addr));
}
__device__ __forceinline__ void mma16816(float* c, const uint32_t* a, uint32_t b0, uint32_t b1) {
    asm volatile("mma.sync.aligned.m16n8k16.row.col.f32.bf16.bf16.f32 "
                 "{%0,%1,%2,%3}, {%4,%5,%6,%7}, {%8,%9}, {%0,%1,%2,%3};"
                 : "+f"(c[0]), "+f"(c[1]), "+f"(c[2]), "+f"(c[3])
                 : "r"(a[0]), "r"(a[1]), "r"(a[2]), "r"(a[3]), "r"(b0), "r"(b1));
}
__device__ __forceinline__ unsigned long long pack_key(float v, unsigned idx) {
    unsigned u = __float_as_uint(v);
    u = (u & 0x80000000u) ? ~u : (u | 0x80000000u);
    return ((unsigned long long)u << 32) | idx;
}

__device__ __forceinline__ void split4(float4 v, uint2& ph, uint2& pl) {
    __nv_bfloat16 h0 = __float2bfloat16(v.x), h1 = __float2bfloat16(v.y),
                  h2 = __float2bfloat16(v.z), h3 = __float2bfloat16(v.w);
    __nv_bfloat16 l0 = __float2bfloat16(v.x - __bfloat162float(h0));
    __nv_bfloat16 l1 = __float2bfloat16(v.y - __bfloat162float(h1));
    __nv_bfloat16 l2 = __float2bfloat16(v.z - __bfloat162float(h2));
    __nv_bfloat16 l3 = __float2bfloat16(v.w - __bfloat162float(h3));
    ph.x = (uint32_t)__bfloat16_as_ushort(h0) | ((uint32_t)__bfloat16_as_ushort(h1) << 16);
    ph.y = (uint32_t)__bfloat16_as_ushort(h2) | ((uint32_t)__bfloat16_as_ushort(h3) << 16);
    pl.x = (uint32_t)__bfloat16_as_ushort(l0) | ((uint32_t)__bfloat16_as_ushort(l1) << 16);
    pl.y = (uint32_t)__bfloat16_as_ushort(l2) | ((uint32_t)__bfloat16_as_ushort(l3) << 16);
}

// ---------------- kernel 1: prep via 32-token transpose tile ----------------
__global__ void k_prep32(const float* __restrict__ z) {
    __shared__ float tile[32 * 257];
    __shared__ float pn[8][33];

    const int tid = threadIdx.x;
    const int tx  = tid & 31;
    const int ty  = tid >> 5;
    const int blk = blockIdx.x;
    const int b   = blk >> 5;
    const int hw0 = (blk & 31) * 32;

    const float* zp = z + (size_t)b * (KDIM * HWSZ) + hw0 + tx;
    float np = 0.0f;
#pragma unroll 8
    for (int cc = 0; cc < 32; cc++) {
        int c = ty * 32 + cc;
        float v = zp[(size_t)c * HWSZ];
        tile[tx * 257 + c] = v;
        np += v * v;
    }
    pn[ty][tx] = np;
    __syncthreads();
    if (tid < 32) {
        float s = 0.0f;
#pragma unroll
        for (int j = 0; j < 8; j++) s += pn[j][tid];
        pn[0][tid] = sqrtf(s);
        g_best[blk * 32 + tid] = 0xFFFFFFFFFFFFFFFFull;
    }
    __syncthreads();
    if (tid == 0) {
        float s = 0.0f;
#pragma unroll
        for (int i = 0; i < 32; i++) s += pn[0][i];
        g_normpart[blk] = s;
    }

#pragma unroll 4
    for (int tok = 0; tok < 32; tok++) {
        const int t = blk * 32 + tok;
        float v = tile[tok * 257 + tid];
        g_zflat[t * KDIM + tid] = v;
        __nv_bfloat16 h = __float2bfloat16(v);
        __nv_bfloat16 l = __float2bfloat16(v - __bfloat162float(h));
        g_z_hi[t * KDIM + tid] = h;
        g_z_lo[t * KDIM + tid] = l;
    }
}

// ---------------- kernel 2: scale + counter reset ----------------
__global__ void k_scale() {
    __shared__ float s[512];
    s[threadIdx.x] = g_normpart[threadIdx.x];
    __syncthreads();
    for (int st = 256; st > 0; st >>= 1) {
        if (threadIdx.x < st) s[threadIdx.x] += s[threadIdx.x + st];
        __syncthreads();
    }
    if (threadIdx.x == 0) {
        float pre_len = s[0] / (float)M_TOK;
        float scale = (pre_len >= FIXLEN) ? (FIXLEN / pre_len) : 1.0f;
        g_scalars[0] = scale;
        g_scalars[1] = 2.0f * scale / FIXLEN;
        g_unit_ctr = 0u;
    }
}

// ---------------- kernel 3 ----------------
__global__ void k_enorm(const float* __restrict__ emb) {
    int w    = threadIdx.x >> 5;
    int lane = threadIdx.x & 31;
    int r    = blockIdx.x * 8 + w;
    const float4* ep = (const float4*)(emb + (size_t)r * KDIM);
    float4 a = ep[lane];
    float4 b = ep[lane + 32];
    float acc = a.x * a.x + a.y * a.y + a.z * a.z + a.w * a.w
              + b.x * b.x + b.y * b.y + b.z * b.z + b.w * b.w;
    uint2 ph, pl;
    split4(a, ph, pl);
    *(uint2*)&g_e_hi[(size_t)r * KDIM + 4 * lane] = ph;
    *(uint2*)&g_e_lo[(size_t)r * KDIM + 4 * lane] = pl;
    split4(b, ph, pl);
    *(uint2*)&g_e_hi[(size_t)r * KDIM + 128 + 4 * lane] = ph;
    *(uint2*)&g_e_lo[(size_t)r * KDIM + 128 + 4 * lane] = pl;
#pragma unroll
    for (int s = 16; s > 0; s >>= 1)
        acc += __shfl_down_sync(0xffffffffu, acc, s);
    if (lane == 0) g_enorm2[r] = acc;
}

// ---------------- kernel 4: persistent HMMA bf16x3, 2 CTAs/SM, pair barriers ----
// CTA = 256 threads (8 warps, 2m x 4n, warp tile 32x32), m-tile 64 tokens.
// Run = m-tile x 2048 n-cols = 128 chunks of 128n x 64k (16KB, 3 buffers).
// Each warp PAIR (wm 0,1 of one wn) loads and consumes only its own 32 B-rows
// (4KB section) per chunk -> per-chunk sync is a named pair barrier, not
// __syncthreads. Block sync only at chunk 0 (A visibility) and run boundary.
#define SM_A_BYTES 65536
#define SM_B_BYTES 16384

__device__ __forceinline__ uint32_t a_sw(int row, int col) {   // col in [0,512)
    return (uint32_t)(row * 1024 + ((col >> 6) << 7)
           + (((((col >> 3) & 7) ^ (row & 7))) << 4) + ((col & 7) << 1));
}
__device__ __forceinline__ uint32_t b_sw64(int row, int col) { // col in [0,64)
    return (uint32_t)(row * 128 + ((((col >> 3) ^ (row & 7))) << 4) + ((col & 7) << 1));
}

extern __shared__ char dsm[];

// 4 k16-steps over one 64k-wide B chunk. DUAL: also multiply the a_lo block
// (at +512 bytes = cols 256..). ablk = byte offset of the A 64-col hi block.
template <bool DUAL>
__device__ __forceinline__ void pass4(
    uint32_t As, uint32_t Bb, uint32_t ablk,
    const uint32_t* aoff0, const uint32_t* aoff1,
    const uint32_t* boff0, const uint32_t* boff1,
    float acc[2][4][4])
{
    const uint32_t* aoff[2] = { aoff0, aoff1 };
    const uint32_t* boff[2] = { boff0, boff1 };
    uint32_t ah[2][2][4], al[2][2][4], br[2][2][4];
#pragma unroll
    for (int mt = 0; mt < 2; mt++) {
        ldsm4(ah[0][mt], As + aoff[mt][0] + ablk);
        if (DUAL) ldsm4(al[0][mt], As + aoff[mt][0] + ablk + 512u);
    }
#pragma unroll
    for (int np = 0; np < 2; np++)
        ldsm4(br[0][np], Bb + boff[np][0]);
#pragma unroll
    for (int kk = 0; kk < 4; kk++) {
        const int cur = kk & 1, nxt = cur ^ 1;
        if (kk < 3) {
            const int ph = kk + 1;
#pragma unroll
            for (int mt = 0; mt < 2; mt++) {
                ldsm4(ah[nxt][mt], As + aoff[mt][ph] + ablk);
                if (DUAL) ldsm4(al[nxt][mt], As + aoff[mt][ph] + ablk + 512u);
            }
#pragma unroll
            for (int np = 0; np < 2; np++)
                ldsm4(br[nxt][np], Bb + boff[np][ph]);
        }
#pragma unroll
        for (int mt = 0; mt < 2; mt++)
#pragma unroll
            for (int nt = 0; nt < 4; nt++)
                mma16816(acc[mt][nt], ah[cur][mt],
                         br[cur][nt >> 1][(nt & 1) * 2], br[cur][nt >> 1][(nt & 1) * 2 + 1]);
        if (DUAL) {
#pragma unroll
            for (int mt = 0; mt < 2; mt++)
#pragma unroll
                for (int nt = 0; nt < 4; nt++)
                    mma16816(acc[mt][nt], al[cur][mt],
                             br[cur][nt >> 1][(nt & 1) * 2], br[cur][nt >> 1][(nt & 1) * 2 + 1]);
        }
    }
}

__global__ void __launch_bounds__(256, 2) k_gemm_p() {
    __shared__ unsigned s_run;

    const int tid  = threadIdx.x;
    const int lane = tid & 31;
    const int wid  = tid >> 5;
    const int wm   = wid & 1;        // 2 warps along m
    const int wn   = wid >> 1;       // 4 warps along n (pair id)
    const int g    = lane >> 2;
    const int cc   = lane & 3;
    const int sub  = lane >> 3;
    const int r8   = lane & 7;

    uint32_t raw  = smem_u32(dsm);
    uint32_t base = (raw + 255u) & ~255u;
    const uint32_t As = base;
    const uint32_t Bbuf0 = base + SM_A_BYTES;

    const int arow_base = wm * 32 + ((sub & 1) << 3) + r8;   // < 64
    const int ak8       = (sub >> 1) & 1;
    const int brow_base = wn * 32 + ((sub >> 1) << 3) + r8;  // < 128
    const int bk8       = sub & 1;
    const int barid     = 1 + wn;

    uint32_t aoff0[4], aoff1[4], boff0[4], boff1[4];
#pragma unroll
    for (int ph = 0; ph < 4; ph++) {
        int ar0 = arow_base, ar1 = arow_base + 16;
        aoff0[ph] = (uint32_t)(ar0 * 1024 + ((((2 * ph + ak8) & 7) ^ (ar0 & 7)) << 4));
        aoff1[ph] = (uint32_t)(ar1 * 1024 + ((((2 * ph + ak8) & 7) ^ (ar1 & 7)) << 4));
        int br0 = brow_base, br1 = brow_base + 16;
        boff0[ph] = (uint32_t)(br0 * 128 + ((((2 * ph + bk8) & 7) ^ (br0 & 7)) << 4));
        boff1[ph] = (uint32_t)(br1 * 128 + ((((2 * ph + bk8) & 7) ^ (br1 & 7)) << 4));
    }

    // pair-local cp.async offsets: this pair loads B rows [wn*32, wn*32+32)
    // of each chunk = 4KB = 4 x 16B lines per thread (64 threads).
    const int pairlane = tid & 63;
    uint32_t bdst[4], bsoff[4];
#pragma unroll
    for (int i = 0; i < 4; i++) {
        int f = pairlane + i * 64;          // 0..255 lines of the 4KB section
        int row = wn * 32 + (f >> 3);       // row within the 128-row chunk
        int k = (f & 7) * 8;
        bdst[i]  = b_sw64(row, k);
        bsoff[i] = (uint32_t)(row * KDIM + k);
    }

    const float alpha = g_scalars[1];
    const float2* e2 = (const float2*)g_enorm2;

    float bestv[4];
    int   besti[4];
    int   cur_m = -1;

    float acc[2][4][4];
#pragma unroll
    for (int a = 0; a < 2; a++)
#pragma unroll
        for (int b = 0; b < 4; b++)
#pragma unroll
            for (int d = 0; d < 4; d++) acc[a][b][d] = 0.0f;

    while (true) {
        __syncthreads();   // run boundary: buffers free, s_run reusable
        if (tid == 0) s_run = atomicAdd(&g_unit_ctr, 1u);
        __syncthreads();
        const unsigned run = s_run;
        if (run >= RUNS_TOTAL) break;

        const int m_tile = (int)(run >> 3);          // 0..255 (64 tokens each)
        const int nbase  = (int)(run & 7u) * 2048;

        if (m_tile != cur_m) {
            if (cur_m >= 0) {
#pragma unroll
                for (int mt = 0; mt < 2; mt++)
#pragma unroll
                    for (int h = 0; h < 2; h++) {
                        int mloc = wm * 32 + mt * 16 + h * 8 + g;
                        atomicMin(&g_best[cur_m * 64 + mloc],
                                  pack_key(bestv[mt * 2 + h], (unsigned)besti[mt * 2 + h]));
                    }
            }
#pragma unroll
            for (int i = 0; i < 4; i++) { bestv[i] = 3.4e38f; besti[i] = 0; }
            cur_m = m_tile;
            const int m0 = m_tile * 64;
#pragma unroll
            for (int seg = 0; seg < 2; seg++) {
                const __nv_bfloat16* src = seg ? g_z_lo : g_z_hi;
                for (int f = tid; f < 2048; f += 256) {
                    int row = f >> 5, k = (f & 31) * 8;
                    cp_async16(As + a_sw(row, seg * 256 + k),
                               src + (size_t)(m0 + row) * KDIM + k);
                }
            }
            cp_commit();
        }

        // prologue: pair-local sections of chunks 0 (e_hi k0) and 1 (e_hi k64)
        {
            const __nv_bfloat16* s0 = g_e_hi + (size_t)nbase * KDIM;
#pragma unroll
            for (int i = 0; i < 4; i++) cp_async16(Bbuf0 + bdst[i], s0 + bsoff[i]);
            cp_commit();
            const __nv_bfloat16* s1 = s0 + 64;
#pragma unroll
            for (int i = 0; i < 4; i++) cp_async16(Bbuf0 + SM_B_BYTES + bdst[i], s1 + bsoff[i]);
            cp_commit();
        }

#pragma unroll 1
        for (int c = 0; c < 128; c++) {
            if (c < 127) cp_wait<1>(); else cp_wait<0>();
            if (c == 0) __syncthreads();      // A visibility (cross-thread)
            else        bar_pair(barid);      // pair-local chunk handoff
            if (c < 126) {
                const int cn = c + 2;
                const int s  = cn >> 3, p = cn & 7;
                const __nv_bfloat16* src = ((p < 4) ? g_e_hi : g_e_lo)
                    + (size_t)(nbase + s * 128) * KDIM + (p & 3) * 64;
                const uint32_t dst = Bbuf0 + (uint32_t)(cn % 3) * SM_B_BYTES;
#pragma unroll
                for (int i = 0; i < 4; i++) cp_async16(dst + bdst[i], src + bsoff[i]);
                cp_commit();
            }
            const int p = c & 7;
            const uint32_t Bb = Bbuf0 + (uint32_t)(c % 3) * SM_B_BYTES;
            // e_lo chunks multiply the a_HI block at (p-4)*128 (cross term).
            if (p < 4) {
                const uint32_t ablk = (uint32_t)(p * 128);
                pass4<true>(As, Bb, ablk, aoff0, aoff1, boff0, boff1, acc);
            } else {
                const uint32_t ablk = (uint32_t)((p - 4) * 128);
                pass4<false>(As, Bb, ablk, aoff0, aoff1, boff0, boff1, acc);
            }

            if (p == 7) {
                const int n0 = nbase + (c >> 3) * 128;
#pragma unroll
                for (int mt = 0; mt < 2; mt++) {
#pragma unroll
                    for (int nt = 0; nt < 4; nt++) {
                        const int nloc = wn * 32 + nt * 8 + 2 * cc;
                        const int gn = n0 + nloc;
                        float2 ev = __ldg(e2 + ((unsigned)gn >> 1));
                        float v0 = fmaf(-alpha, acc[mt][nt][0], ev.x);
                        float v1 = fmaf(-alpha, acc[mt][nt][1], ev.y);
                        float v2 = fmaf(-alpha, acc[mt][nt][2], ev.x);
                        float v3 = fmaf(-alpha, acc[mt][nt][3], ev.y);
                        const int i0 = mt * 2, i1 = mt * 2 + 1;
                        if (v0 < bestv[i0]) { bestv[i0] = v0; besti[i0] = gn; }
                        if (v1 < bestv[i0]) { bestv[i0] = v1; besti[i0] = gn + 1; }
                        if (v2 < bestv[i1]) { bestv[i1] = v2; besti[i1] = gn; }
                        if (v3 < bestv[i1]) { bestv[i1] = v3; besti[i1] = gn + 1; }
                        acc[mt][nt][0] = 0.0f; acc[mt][nt][1] = 0.0f;
                        acc[mt][nt][2] = 0.0f; acc[mt][nt][3] = 0.0f;
                    }
                }
            }
        }
    }

    if (cur_m >= 0) {
#pragma unroll
        for (int mt = 0; mt < 2; mt++)
#pragma unroll
            for (int h = 0; h < 2; h++) {
                int mloc = wm * 32 + mt * 16 + h * 8 + g;
                atomicMin(&g_best[cur_m * 64 + mloc],
                          pack_key(bestv[mt * 2 + h], (unsigned)besti[mt * 2 + h]));
            }
    }
}

// ---------------- kernel 5: gather via 32-token transpose tile ----------------
__global__ void k_gather32(const float* __restrict__ emb, float* __restrict__ out) {
    __shared__ float tile[32 * 257];
    __shared__ float sred[256];

    const int tid = threadIdx.x;
    const int blk = blockIdx.x;
    const int b   = blk >> 5;
    const int hw0 = (blk & 31) * 32;

    const float scale = g_scalars[0];
    float lsum = 0.0f;

#pragma unroll 4
    for (int tok = 0; tok < 32; tok++) {
        const int t = blk * 32 + tok;
        const int idx = (int)(unsigned)(g_best[t] & 0xFFFFFFFFull);
        float zq = emb[(size_t)idx * KDIM + tid] * FIXLEN;
        float zt = g_zflat[t * KDIM + tid] * scale;
        float d = zq - zt;
        lsum += d * d;
        tile[tok * 257 + tid] = zq;
    }
    __syncthreads();

    const int tx = tid & 31;
    const int ty = tid >> 5;
    float* op = out + (size_t)b * (KDIM * HWSZ) + hw0 + tx;
#pragma unroll 8
    for (int ccc = 0; ccc < 32; ccc++) {
        int c = ty * 32 + ccc;
        op[(size_t)c * HWSZ] = tile[tx * 257 + c];
    }

    sred[tid] = lsum;
    __syncthreads();
    for (int s = 128; s > 0; s >>= 1) {
        if (tid < s) sred[tid] += sred[tid + s];
        __syncthreads();
    }
    if (tid == 0) g_diffpart[blk] = sred[0];
}

// ---------------- kernel 6 ----------------
__global__ void k_final(float* __restrict__ out, int out_size) {
    __shared__ float s[512];
    s[threadIdx.x] = g_diffpart[threadIdx.x];
    __syncthreads();
    for (int st = 256; st > 0; st >>= 1) {
        if (threadIdx.x < st) s[threadIdx.x] += s[threadIdx.x + st];
        __syncthreads();
    }
    float diff = 0.25f * s[0] / (float)(M_TOK * KDIM);
    if (threadIdx.x == 0 && out_size > NZ) out[NZ] = diff;
    if (out_size >= NZ + 1 + M_TOK) {
        for (int t = threadIdx.x; t < M_TOK; t += 512)
            out[NZ + 1 + t] = (float)(unsigned)(g_best[t] & 0xFFFFFFFFull);
    }
}

// ---------------- launch ----------------
extern "C" void kernel_launch(void* const* d_in, const int* in_sizes, int n_in,
                              void* d_out, int out_size) {
    const float* z   = (const float*)d_in[0];
    const float* emb = (const float*)d_in[1];
    float* out = (float*)d_out;
    (void)in_sizes; (void)n_in;

    const int gemm_smem = 256 + SM_A_BYTES + 3 * SM_B_BYTES;  // 114,944 B/CTA
    cudaFuncSetAttribute(k_gemm_p, cudaFuncAttributeMaxDynamicSharedMemorySize, gemm_smem);

    k_prep32<<<512, 256>>>(z);
    k_scale<<<1, 512>>>();
    k_enorm<<<N_EMB / 8, 256>>>(emb);
    k_gemm_p<<<NUM_CTAS, 256, gemm_smem>>>();
    k_gather32<<<512, 256>>>(emb, out);
    k_final<<<1, 512>>>(out, out_size);
}